// round 1
// baseline (speedup 1.0000x reference)
#include <cuda_runtime.h>
#include <cuda_bf16.h>
#include <cstddef>

#define HW 16384
#define DIMC 256
#define SCALE 0.17677669529663689f
#define EPSBN 1e-5f

// ---------------- scratch ----------------
__device__ float g_y1[2 * 256 * HW];   // relu(bn1(conv1(x)))
__device__ float g_q [2 * 256 * HW];   // q conv
__device__ float g_kv[2 * 512 * HW];   // kv conv
__device__ float g_y2[2 * 256 * HW];   // relu(bna(attn_out))

// ---------------- GEMM: Out[o,p] = sum_c W[o,c] * X[c,p], per batch z ----------------
// MODE 0: plain   MODE 1: relu(bn(.))   MODE 2: relu(resid + gamma*relu(bn(.)))
template<int MODE>
__global__ __launch_bounds__(256) void gemm_conv(
    const float* __restrict__ X, const float* __restrict__ Wm, float* __restrict__ Out, int M,
    const float* __restrict__ bw, const float* __restrict__ bb,
    const float* __restrict__ bm, const float* __restrict__ bv,
    const float* __restrict__ gamma, const float* __restrict__ resid)
{
    __shared__ float Ws[16][68];
    __shared__ float Xs[16][128];
    const int tid = threadIdx.x;
    const int p0 = blockIdx.x * 128;
    const int o0 = blockIdx.y * 64;
    const int z  = blockIdx.z;
    const float* Xb = X + (size_t)z * 256 * HW;
    float* Ob = Out + (size_t)z * M * HW;
    const int tx = tid & 15, ty = tid >> 4;

    float acc[4][8];
#pragma unroll
    for (int ii = 0; ii < 4; ii++)
#pragma unroll
        for (int jj = 0; jj < 8; jj++) acc[ii][jj] = 0.f;

    const int wrow = tid >> 2;          // 0..63
    const int wc4  = (tid & 3) * 4;     // 0,4,8,12

    for (int k0 = 0; k0 < 256; k0 += 16) {
        float4 w4 = *(const float4*)&Wm[(o0 + wrow) * 256 + k0 + wc4];
        Ws[wc4 + 0][wrow] = w4.x;
        Ws[wc4 + 1][wrow] = w4.y;
        Ws[wc4 + 2][wrow] = w4.z;
        Ws[wc4 + 3][wrow] = w4.w;
#pragma unroll
        for (int it = 0; it < 2; it++) {
            int idx = tid + it * 256;
            int row = idx >> 5, cg = idx & 31;
            float4 xv = *(const float4*)&Xb[(size_t)(k0 + row) * HW + p0 + cg * 4];
            *(float4*)&Xs[row][cg * 4] = xv;
        }
        __syncthreads();
#pragma unroll
        for (int kk = 0; kk < 16; kk++) {
            float4 a4 = *(float4*)&Ws[kk][ty * 4];
            float4 b0 = *(float4*)&Xs[kk][tx * 8];
            float4 b1 = *(float4*)&Xs[kk][tx * 8 + 4];
            float a[4] = {a4.x, a4.y, a4.z, a4.w};
            float bvv[8] = {b0.x, b0.y, b0.z, b0.w, b1.x, b1.y, b1.z, b1.w};
#pragma unroll
            for (int ii = 0; ii < 4; ii++)
#pragma unroll
                for (int jj = 0; jj < 8; jj++)
                    acc[ii][jj] = fmaf(a[ii], bvv[jj], acc[ii][jj]);
        }
        __syncthreads();
    }

#pragma unroll
    for (int ii = 0; ii < 4; ii++) {
        int o = o0 + ty * 4 + ii;
        float mul = 1.f, add = 0.f, gm = 0.f;
        if (MODE >= 1) {
            float inv = bw[o] * rsqrtf(bv[o] + EPSBN);
            mul = inv;
            add = fmaf(-bm[o], inv, bb[o]);
        }
        if (MODE == 2) gm = gamma[o];
        float* orow = &Ob[(size_t)o * HW + p0 + tx * 8];
        const float* rrow = (MODE == 2) ? &resid[((size_t)z * 256 + o) * HW + p0 + tx * 8] : nullptr;
        float outv[8];
#pragma unroll
        for (int jj = 0; jj < 8; jj++) {
            float v = acc[ii][jj];
            if (MODE >= 1) { v = fmaf(v, mul, add); v = fmaxf(v, 0.f); }
            if (MODE == 2) { v = fmaf(gm, v, rrow[jj]); v = fmaxf(v, 0.f); }
            outv[jj] = v;
        }
        *(float4*)&orow[0] = make_float4(outv[0], outv[1], outv[2], outv[3]);
        *(float4*)&orow[4] = make_float4(outv[4], outv[5], outv[6], outv[7]);
    }
}

// ---------------- Halo attention ----------------
// One CTA per (bh in 16, block in 256). 128 threads: 64 q-rows x 2 key-halves
// (each half covers 7 of 14 kh rows; partial softmax states merged at the end).
// Epilogue fuses relu(bna(.)) and writes g_y2.
#define KS 36  // padded K/V row stride (floats)
#define ATTN_SMEM_FLOATS (7056 + 7056 + 2048 + 864 + 864 + 1728 + 1728)

__global__ __launch_bounds__(128) void attn_kernel(
    const float* __restrict__ q, const float* __restrict__ kv,
    const float* __restrict__ hrel, const float* __restrict__ wrel,
    const float* __restrict__ aw, const float* __restrict__ ab,
    const float* __restrict__ am, const float* __restrict__ av,
    float* __restrict__ y2)
{
    extern __shared__ float sm[];
    float* Ksm = sm;             // 196 * 36
    float* Vsm = sm + 7056;      // 196 * 36
    float* Qsm = sm + 14112;     // 64 * 32
    float* RH  = sm + 16160;     // 27 * 32
    float* RW  = sm + 17024;     // 27 * 32
    float* QH  = sm + 17888;     // 64 * 27
    float* QW  = sm + 19616;     // 64 * 27

    const int blk = blockIdx.x, bh = blockIdx.y;
    const int b = bh >> 3, head = bh & 7;
    const int hb = blk >> 4, wb = blk & 15;
    const int tid = threadIdx.x;

    // ---- load Q tile (64 q-positions x 32 dims) ----
    const int qchan = b * 256 + head * 32;
    for (int idx = tid; idx < 2048; idx += 128) {
        int d = idx >> 6, qq = idx & 63;
        int ii = qq >> 3, jj = qq & 7;
        Qsm[qq * 32 + d] =
            q[((size_t)(qchan + d) << 14) + (hb * 8 + ii) * 128 + wb * 8 + jj];
    }
    for (int idx = tid; idx < 864; idx += 128) { RH[idx] = hrel[idx]; RW[idx] = wrel[idx]; }

    // ---- gather K/V halo window (196 x 32 each), zero-padded at borders ----
    const int r0 = hb * 8 - 3, c0 = wb * 8 - 3;
    const int kvchan = b * 512 + head * 64;
    for (int e = tid; e < 196 * 64; e += 128) {
        int dd = e / 196, kp = e - dd * 196;
        int kh = kp / 14, kw = kp - kh * 14;
        int r = r0 + kh, c = c0 + kw;
        float val = 0.f;
        if ((unsigned)r < 128u && (unsigned)c < 128u)
            val = kv[((size_t)(kvchan + dd) << 14) + r * 128 + c];
        if (dd < 32) Ksm[kp * KS + dd] = val;
        else         Vsm[kp * KS + dd - 32] = val;
    }
    __syncthreads();

    // ---- per-row relative position dots: QH[t][r] = Q_t . hrel[r], QW likewise ----
    for (int idx = tid; idx < 1728; idx += 128) {
        int row = idx / 27, r = idx - row * 27;
        float s1 = 0.f, s2 = 0.f;
        const float* qr = Qsm + row * 32;
        const float* hr = RH + r * 32;
        const float* wr = RW + r * 32;
#pragma unroll 8
        for (int d = 0; d < 32; d++) {
            s1 = fmaf(qr[d], hr[d], s1);
            s2 = fmaf(qr[d], wr[d], s2);
        }
        QH[idx] = s1; QW[idx] = s2;
    }
    __syncthreads();

    const int half = tid >> 6, t = tid & 63;
    const int i = t >> 3, j = t & 7;

    float4 Qr4[8];
    const float4* qrow4 = (const float4*)(Qsm + t * 32);
#pragma unroll
    for (int u = 0; u < 8; u++) {
        float4 v = qrow4[u];
        v.x *= SCALE; v.y *= SCALE; v.z *= SCALE; v.w *= SCALE;
        Qr4[u] = v;
    }

    float m = -1e30f, l = 0.f;
    float4 acc4[8] = {};

    const float* QHrow = QH + t * 27 + 13 - i;   // index with +kh
    const float* QWrow = QW + t * 27 + 13 - j;   // index with +kw

    for (int kh = half * 7; kh < half * 7 + 7; kh++) {
        float ph = QHrow[kh];
        float s[14];
        const float* Kb = Ksm + kh * 14 * KS;
#pragma unroll
        for (int kw = 0; kw < 14; kw++) {
            const float4* K4 = (const float4*)(Kb + kw * KS);
            float d0 = 0.f, d1 = 0.f, d2 = 0.f, d3 = 0.f;
#pragma unroll
            for (int u = 0; u < 8; u++) {
                float4 k4 = K4[u];
                d0 = fmaf(Qr4[u].x, k4.x, d0);
                d1 = fmaf(Qr4[u].y, k4.y, d1);
                d2 = fmaf(Qr4[u].z, k4.z, d2);
                d3 = fmaf(Qr4[u].w, k4.w, d3);
            }
            s[kw] = (d0 + d1) + (d2 + d3) + ph + QWrow[kw];
        }
        float cmax = s[0];
#pragma unroll
        for (int kw = 1; kw < 14; kw++) cmax = fmaxf(cmax, s[kw]);
        float mn = fmaxf(m, cmax);
        float corr = __expf(m - mn);
        m = mn;
        l *= corr;
#pragma unroll
        for (int u = 0; u < 8; u++) {
            acc4[u].x *= corr; acc4[u].y *= corr; acc4[u].z *= corr; acc4[u].w *= corr;
        }
        const float* Vb = Vsm + kh * 14 * KS;
#pragma unroll
        for (int kw = 0; kw < 14; kw++) {
            float p = __expf(s[kw] - m);
            l += p;
            const float4* V4 = (const float4*)(Vb + kw * KS);
#pragma unroll
            for (int u = 0; u < 8; u++) {
                float4 v4 = V4[u];
                acc4[u].x = fmaf(p, v4.x, acc4[u].x);
                acc4[u].y = fmaf(p, v4.y, acc4[u].y);
                acc4[u].z = fmaf(p, v4.z, acc4[u].z);
                acc4[u].w = fmaf(p, v4.w, acc4[u].w);
            }
        }
    }

    // ---- merge the two halves (reuse Ksm as buffer) ----
    __syncthreads();
    float* mb = Ksm;
    if (half == 1) {
        float4* mb4 = (float4*)(mb + t * KS);
#pragma unroll
        for (int u = 0; u < 8; u++) mb4[u] = acc4[u];
        mb[t * KS + 32] = m;
        mb[t * KS + 33] = l;
    }
    __syncthreads();
    if (half == 0) {
        float m2 = mb[t * KS + 32], l2 = mb[t * KS + 33];
        float mn = fmaxf(m, m2);
        float c1 = __expf(m - mn), c2 = __expf(m2 - mn);
        l = l * c1 + l2 * c2;
        const float4* mb4 = (const float4*)(mb + t * KS);
#pragma unroll
        for (int u = 0; u < 8; u++) {
            float4 o4 = mb4[u];
            acc4[u].x = acc4[u].x * c1 + o4.x * c2;
            acc4[u].y = acc4[u].y * c1 + o4.y * c2;
            acc4[u].z = acc4[u].z * c1 + o4.z * c2;
            acc4[u].w = acc4[u].w * c1 + o4.w * c2;
        }
        float invl = 1.f / l;
        size_t obase = ((size_t)(b * 256 + head * 32) << 14) + (hb * 8 + i) * 128 + wb * 8 + j;
#pragma unroll
        for (int u = 0; u < 8; u++) {
            float vals[4] = {acc4[u].x, acc4[u].y, acc4[u].z, acc4[u].w};
#pragma unroll
            for (int cc = 0; cc < 4; cc++) {
                int d = u * 4 + cc;
                int ch = head * 32 + d;
                float inv  = aw[ch] * rsqrtf(av[ch] + EPSBN);
                float bias = fmaf(-am[ch], inv, ab[ch]);
                float v = fmaf(vals[cc] * invl, inv, bias);
                v = fmaxf(v, 0.f);
                y2[obase + ((size_t)d << 14)] = v;
            }
        }
    }
}

// ---------------- launch ----------------
extern "C" void kernel_launch(void* const* d_in, const int* in_sizes, int n_in,
                              void* d_out, int out_size)
{
    const float* x     = (const float*)d_in[0];
    const float* w1    = (const float*)d_in[1];
    const float* qw    = (const float*)d_in[2];
    const float* kvw   = (const float*)d_in[3];
    const float* w3    = (const float*)d_in[4];
    const float* hrel  = (const float*)d_in[5];
    const float* wrel  = (const float*)d_in[6];
    const float* bn1w  = (const float*)d_in[7];
    const float* bn1b  = (const float*)d_in[8];
    const float* bn1m  = (const float*)d_in[9];
    const float* bn1v  = (const float*)d_in[10];
    const float* bnaw  = (const float*)d_in[11];
    const float* bnab  = (const float*)d_in[12];
    const float* bnam  = (const float*)d_in[13];
    const float* bnav  = (const float*)d_in[14];
    const float* bn3w  = (const float*)d_in[15];
    const float* bn3b  = (const float*)d_in[16];
    const float* bn3m  = (const float*)d_in[17];
    const float* bn3v  = (const float*)d_in[18];
    const float* gamma = (const float*)d_in[19];
    float* out = (float*)d_out;

    float *p_y1, *p_q, *p_kv, *p_y2;
    cudaGetSymbolAddress((void**)&p_y1, g_y1);
    cudaGetSymbolAddress((void**)&p_q,  g_q);
    cudaGetSymbolAddress((void**)&p_kv, g_kv);
    cudaGetSymbolAddress((void**)&p_y2, g_y2);

    const int attn_smem = ATTN_SMEM_FLOATS * 4;
    cudaFuncSetAttribute(attn_kernel, cudaFuncAttributeMaxDynamicSharedMemorySize, attn_smem);

    dim3 blk(256);
    // 1) y1 = relu(bn1(w1 @ x))
    gemm_conv<1><<<dim3(128, 4, 2), blk>>>(x, w1, p_y1, 256,
                                           bn1w, bn1b, bn1m, bn1v, nullptr, nullptr);
    // 2) q = q_w @ y1
    gemm_conv<0><<<dim3(128, 4, 2), blk>>>(p_y1, qw, p_q, 256,
                                           nullptr, nullptr, nullptr, nullptr, nullptr, nullptr);
    // 3) kv = kv_w @ y1
    gemm_conv<0><<<dim3(128, 8, 2), blk>>>(p_y1, kvw, p_kv, 512,
                                           nullptr, nullptr, nullptr, nullptr, nullptr, nullptr);
    // 4) attention + fused relu(bna(.))
    attn_kernel<<<dim3(256, 16), 128, attn_smem>>>(p_q, p_kv, hrel, wrel,
                                                   bnaw, bnab, bnam, bnav, p_y2);
    // 5) out = relu(x + gamma*relu(bn3(w3 @ y2)))
    gemm_conv<2><<<dim3(128, 4, 2), blk>>>(p_y2, w3, out, 256,
                                           bn3w, bn3b, bn3m, bn3v, gamma, x);
}